// round 6
// baseline (speedup 1.0000x reference)
#include <cuda_runtime.h>

// ---------------- problem constants ----------------
#define BT_   2048      // B*T
#define D_    512
#define HID_  256
#define DK_   100
#define KB_   8
#define R_    64
#define CPER_ 1250
#define NC_   10000

// ---------------- scratch (no allocations allowed) ----------------
__device__ float    g_h [BT_ * HID_];        // 2 MB
__device__ float    g_ur[BT_ * KB_ * R_];    // 4 MB
__device__ unsigned g_sel[320];              // 10000-bit membership bitmap

// ---------------- zero the selection bitmap ----------------
__global__ void zero_sel_kernel() {
    int t = threadIdx.x;
    if (t < 320) g_sel[t] = 0u;
}

// ---------------- generic tiled GEMM: C = act(A[M,K] @ B[N,K]^T + bias) ----
// BM=128, BN=64, BK=32, 256 threads, 8x4 register tile.
__global__ __launch_bounds__(256) void gemm_nt_kernel(
    const float* __restrict__ A,
    const float* __restrict__ B, int ldb,
    const float* __restrict__ bias,
    int K, int relu, int dst)
{
    __shared__ float As[128][33];
    __shared__ float Bs[64][33];
    const int m0 = blockIdx.y * 128;
    const int n0 = blockIdx.x * 64;
    const int tid = threadIdx.x;
    const int rr = (tid >> 4) << 3;   // 0..120 step 8
    const int cc = (tid & 15) << 2;   // 0..60 step 4

    float acc[8][4];
    #pragma unroll
    for (int i = 0; i < 8; i++)
        #pragma unroll
        for (int j = 0; j < 4; j++) acc[i][j] = 0.f;

    for (int k0 = 0; k0 < K; k0 += 32) {
        #pragma unroll
        for (int l = 0; l < 4; l++) {               // A tile: 128x32
            int idx = tid + l * 256;
            int row = idx >> 3, c4 = (idx & 7) << 2;
            float4 v = *(const float4*)&A[(size_t)(m0 + row) * D_ + k0 + c4];
            As[row][c4 + 0] = v.x; As[row][c4 + 1] = v.y;
            As[row][c4 + 2] = v.z; As[row][c4 + 3] = v.w;
        }
        #pragma unroll
        for (int l = 0; l < 2; l++) {               // B tile: 64x32
            int idx = tid + l * 256;
            int row = idx >> 3, c4 = (idx & 7) << 2;
            float4 v = *(const float4*)&B[(size_t)(n0 + row) * ldb + k0 + c4];
            Bs[row][c4 + 0] = v.x; Bs[row][c4 + 1] = v.y;
            Bs[row][c4 + 2] = v.z; Bs[row][c4 + 3] = v.w;
        }
        __syncthreads();
        #pragma unroll
        for (int kk = 0; kk < 32; kk++) {
            float a[8], b[4];
            #pragma unroll
            for (int i = 0; i < 8; i++) a[i] = As[rr + i][kk];
            #pragma unroll
            for (int j = 0; j < 4; j++) b[j] = Bs[cc + j][kk];
            #pragma unroll
            for (int i = 0; i < 8; i++)
                #pragma unroll
                for (int j = 0; j < 4; j++)
                    acc[i][j] = fmaf(a[i], b[j], acc[i][j]);
        }
        __syncthreads();
    }

    float* C   = dst ? g_ur : g_h;
    int    ldc = dst ? (KB_ * R_) : HID_;
    float4 bv = make_float4(0.f, 0.f, 0.f, 0.f);
    if (bias) bv = make_float4(bias[n0 + cc], bias[n0 + cc + 1],
                               bias[n0 + cc + 2], bias[n0 + cc + 3]);
    #pragma unroll
    for (int i = 0; i < 8; i++) {
        float4 v;
        v.x = acc[i][0] + bv.x;
        v.y = acc[i][1] + bv.y;
        v.z = acc[i][2] + bv.z;
        v.w = acc[i][3] + bv.w;
        if (relu) {
            v.x = fmaxf(v.x, 0.f); v.y = fmaxf(v.y, 0.f);
            v.z = fmaxf(v.z, 0.f); v.w = fmaxf(v.w, 0.f);
        }
        // ldc (256 or 512) and n0+cc are multiples of 4 -> 16B aligned
        *(float4*)&C[(size_t)(m0 + rr + i) * ldc + n0 + cc] = v;
    }
}

// ---------------- candidate scores + stable descending rank -> sel bitmap --
// One block per row, 128 threads.
__global__ __launch_bounds__(128) void candidate_kernel(
    const float* __restrict__ W2,
    const float* __restrict__ b2,
    const int*   __restrict__ idx_base)
{
    __shared__ float hr[HID_];
    __shared__ float sc[DK_];
    const int row = blockIdx.x;
    const int tid = threadIdx.x;

    hr[tid]       = g_h[(size_t)row * HID_ + tid];
    hr[tid + 128] = g_h[(size_t)row * HID_ + tid + 128];
    __syncthreads();

    if (tid < DK_) {
        float s = b2[tid];
        const float* w = W2 + (size_t)tid * HID_;
        #pragma unroll 8
        for (int i = 0; i < HID_; i++) s = fmaf(hr[i], w[i], s);
        sc[tid] = s;
    }
    __syncthreads();

    if (tid < DK_) {
        const float sv = sc[tid];
        int r = 0;
        // stable descending rank: matches jax.lax.top_k tie-breaking
        for (int u = 0; u < DK_; u++) {
            float su = sc[u];
            r += (su > sv) || (su == sv && u < tid);
        }
        int cls = tid + idx_base[r];
        cls = min(max(cls, 0), NC_ - 1);
        atomicOr(&g_sel[cls >> 5], 1u << (cls & 31));
    }
}

// ---------------- masked low-rank output GEMM --------------------------
// out[m, k*1250 + n] = sel ? (ur[m, k*64:..] . V[k,n,:]) + bias : bias
// Grid: (ceil(1250/64)=20, 2048/128=16, 8). Same 128x64x32 tiling.
__global__ __launch_bounds__(256) void svd_out_kernel(
    const float* __restrict__ V,
    const float* __restrict__ bias,
    float* __restrict__ out)
{
    __shared__ float As[128][33];
    __shared__ float Bs[64][33];
    const int k  = blockIdx.z;
    const int m0 = blockIdx.y * 128;
    const int n0 = blockIdx.x * 64;
    const int tid = threadIdx.x;
    const int rr = (tid >> 4) << 3;
    const int cc = (tid & 15) << 2;
    const float* Vk = V + (size_t)k * CPER_ * R_;   // 80000*k: multiple of 4

    float acc[8][4];
    #pragma unroll
    for (int i = 0; i < 8; i++)
        #pragma unroll
        for (int j = 0; j < 4; j++) acc[i][j] = 0.f;

    for (int k0 = 0; k0 < R_; k0 += 32) {
        #pragma unroll
        for (int l = 0; l < 4; l++) {               // ur tile: 128x32
            int idx = tid + l * 256;
            int row = idx >> 3, c4 = (idx & 7) << 2;
            float4 v = *(const float4*)&g_ur[(size_t)(m0 + row) * (KB_ * R_) + k * R_ + k0 + c4];
            As[row][c4 + 0] = v.x; As[row][c4 + 1] = v.y;
            As[row][c4 + 2] = v.z; As[row][c4 + 3] = v.w;
        }
        #pragma unroll
        for (int l = 0; l < 2; l++) {               // V tile: 64x32 (row guard)
            int idx = tid + l * 256;
            int row = idx >> 3, c4 = (idx & 7) << 2;
            float4 v = make_float4(0.f, 0.f, 0.f, 0.f);
            if (n0 + row < CPER_)
                v = *(const float4*)&Vk[(size_t)(n0 + row) * R_ + k0 + c4];
            Bs[row][c4 + 0] = v.x; Bs[row][c4 + 1] = v.y;
            Bs[row][c4 + 2] = v.z; Bs[row][c4 + 3] = v.w;
        }
        __syncthreads();
        #pragma unroll
        for (int kk = 0; kk < 32; kk++) {
            float a[8], b[4];
            #pragma unroll
            for (int i = 0; i < 8; i++) a[i] = As[rr + i][kk];
            #pragma unroll
            for (int j = 0; j < 4; j++) b[j] = Bs[cc + j][kk];
            #pragma unroll
            for (int i = 0; i < 8; i++)
                #pragma unroll
                for (int j = 0; j < 4; j++)
                    acc[i][j] = fmaf(a[i], b[j], acc[i][j]);
        }
        __syncthreads();
    }

    const int col0 = n0 + cc;                 // first of 4 contiguous columns
    if (col0 + 3 < CPER_) {
        const int cg0 = k * CPER_ + col0;     // NOTE: k*1250 -> cg0 % 4 in {0,2}
        float4 bs = make_float4(bias[cg0], bias[cg0 + 1], bias[cg0 + 2], bias[cg0 + 3]);
        float m0f = (float)((g_sel[(cg0    ) >> 5] >> ((cg0    ) & 31)) & 1u);
        float m1f = (float)((g_sel[(cg0 + 1) >> 5] >> ((cg0 + 1) & 31)) & 1u);
        float m2f = (float)((g_sel[(cg0 + 2) >> 5] >> ((cg0 + 2) & 31)) & 1u);
        float m3f = (float)((g_sel[(cg0 + 3) >> 5] >> ((cg0 + 3) & 31)) & 1u);
        if ((cg0 & 3) == 0) {
            // 16B-aligned: STG.128
            #pragma unroll
            for (int i = 0; i < 8; i++) {
                float4 v;
                v.x = fmaf(m0f, acc[i][0], bs.x);
                v.y = fmaf(m1f, acc[i][1], bs.y);
                v.z = fmaf(m2f, acc[i][2], bs.z);
                v.w = fmaf(m3f, acc[i][3], bs.w);
                *(float4*)&out[(size_t)(m0 + rr + i) * NC_ + cg0] = v;
            }
        } else {
            // cg0 is always even -> 8B-aligned: 2x STG.64
            #pragma unroll
            for (int i = 0; i < 8; i++) {
                float2 v01, v23;
                v01.x = fmaf(m0f, acc[i][0], bs.x);
                v01.y = fmaf(m1f, acc[i][1], bs.y);
                v23.x = fmaf(m2f, acc[i][2], bs.z);
                v23.y = fmaf(m3f, acc[i][3], bs.w);
                float* p = &out[(size_t)(m0 + rr + i) * NC_ + cg0];
                *(float2*)(p)     = v01;
                *(float2*)(p + 2) = v23;
            }
        }
    } else {
        #pragma unroll
        for (int j = 0; j < 4; j++) {
            int col = col0 + j;
            if (col >= CPER_) continue;
            int cg = k * CPER_ + col;
            unsigned bit = (g_sel[cg >> 5] >> (cg & 31)) & 1u;
            float bs = bias[cg];
            #pragma unroll
            for (int i = 0; i < 8; i++) {
                float v = bs;
                if (bit) v += acc[i][j];
                out[(size_t)(m0 + rr + i) * NC_ + cg] = v;
            }
        }
    }
}

// ---------------- launch ----------------
extern "C" void kernel_launch(void* const* d_in, const int* in_sizes, int n_in,
                              void* d_out, int out_size)
{
    const float* x        = (const float*)d_in[0];
    const float* W1       = (const float*)d_in[1];
    const float* b1       = (const float*)d_in[2];
    const float* W2       = (const float*)d_in[3];
    const float* b2       = (const float*)d_in[4];
    const float* U        = (const float*)d_in[5];
    const float* V        = (const float*)d_in[6];
    const float* bias     = (const float*)d_in[7];
    const int*   idx_base = (const int*)d_in[8];
    float* out = (float*)d_out;

    (void)in_sizes; (void)n_in; (void)out_size;

    zero_sel_kernel<<<1, 512>>>();

    // h = relu(x @ W1^T + b1)   [2048, 256]
    gemm_nt_kernel<<<dim3(HID_ / 64, BT_ / 128), 256>>>(
        x, W1, D_, b1, D_, /*relu=*/1, /*dst=*/0);

    // scores + ranks -> sel bitmap
    candidate_kernel<<<BT_, 128>>>(W2, b2, idx_base);

    // ur = x @ U^T   (U flattened [512, 512])   [2048, 512]
    gemm_nt_kernel<<<dim3((KB_ * R_) / 64, BT_ / 128), 256>>>(
        x, U, D_, nullptr, D_, /*relu=*/0, /*dst=*/1);

    // out = mask(ur_k @ V_k^T) + bias
    svd_out_kernel<<<dim3(20, BT_ / 128, KB_), 256>>>(V, bias, out);
}